// round 3
// baseline (speedup 1.0000x reference)
#include <cuda_runtime.h>
#include <math.h>

// Problem constants
#define BB 8
#define KK 1024
#define DD 256
#define HH 8
#define RR 4
#define LL 1028      // RR + KK
#define HD 32
#define IMGF 224.0f
#define MAXPF 1023.0f

// ---------------- scratch (device globals; no allocation allowed) ----------
__device__ float g_xfull[BB * LL * DD];        // post-embed, post-rope (pre-LN)
__device__ float g_xn[BB * LL * DD];           // LN(x)
__device__ int   g_allowed[BB * LL];           // key-allowed mask
__device__ int   g_isctx[BB * KK];             // per-token selector
__device__ float g_qkv_c[BB * LL * 3 * DD];    // ctx block QKV
__device__ float g_qkv_t[BB * LL * 3 * DD];    // tgt block QKV
__device__ float g_attn[BB * KK * DD];         // selected attention out (pre-Wo)
__device__ float g_tmp[BB * KK * DD];          // attn @ Wo_sel + bo_sel
__device__ float g_x2[BB * KK * DD];           // x + attn_out (residual 1)
__device__ float g_x2n[BB * KK * DD];          // LN(x2)
__device__ float g_h1[BB * KK * 4 * DD];       // gelu(mlp1)

// ---------------- prep: embed add + rope2d + LN ---------------------------
__global__ __launch_bounds__(256) void prep_kernel(
    const float* __restrict__ x, const int* __restrict__ coords,
    const int* __restrict__ ctxid, const float* __restrict__ tgt_e,
    const float* __restrict__ ctx_e, const float* __restrict__ regs,
    const float* __restrict__ rope, const float* __restrict__ ng,
    const float* __restrict__ nb)
{
    int blk = blockIdx.x;
    int b = blk / LL;
    int l = blk - b * LL;
    int d = threadIdx.x;

    __shared__ float srow[DD];
    __shared__ float red[2][8];

    float v;
    int ic = 1;
    if (l < RR) {
        v = regs[l * DD + d] + ctx_e[d];
    } else {
        int k = l - RR;
        ic = ctxid[b * KK + k] > 0;
        v = x[((size_t)(b * KK + k)) * DD + d] + (ic ? ctx_e[d] : tgt_e[d]);
    }
    srow[d] = v;
    __syncthreads();

    float rv = v;
    if (l >= RR) {
        int k = l - RR;
        int cy = coords[(size_t)(b * KK + k) * 2 + 0];
        int cx = coords[(size_t)(b * KK + k) * 2 + 1];
        float cny = fminf(fmaxf(((float)cy / IMGF) * MAXPF, 0.f), MAXPF);
        float cnx = fminf(fmaxf(((float)cx / IMGF) * MAXPF, 0.f), MAXPF);
        int yi = (int)cny;
        int xi = (int)cnx;
        int j; const float* cp;
        if (d < 128) { j = d >> 1;         cp = rope + ((size_t)xi * 64 + j) * 2; }
        else         { j = (d - 128) >> 1; cp = rope + ((size_t)yi * 64 + j) * 2; }
        float c = cp[0], s = cp[1];
        float p0 = srow[d & ~1];
        float p1 = srow[d | 1];
        rv = (d & 1) ? (p0 * s + p1 * c) : (p0 * c - p1 * s);
    }

    g_xfull[((size_t)(b * LL + l)) * DD + d] = rv;
    if (d == 0) {
        g_allowed[b * LL + l] = (l < RR) ? 1 : ic;
        if (l >= RR) g_isctx[b * KK + (l - RR)] = ic;
    }

    // LayerNorm over 256
    float s1 = rv, s2 = rv * rv;
    #pragma unroll
    for (int o = 16; o; o >>= 1) {
        s1 += __shfl_down_sync(0xffffffffu, s1, o);
        s2 += __shfl_down_sync(0xffffffffu, s2, o);
    }
    int wid = d >> 5, lane = d & 31;
    if (lane == 0) { red[0][wid] = s1; red[1][wid] = s2; }
    __syncthreads();
    if (d == 0) {
        float t1 = 0.f, t2 = 0.f;
        #pragma unroll
        for (int i = 0; i < 8; i++) { t1 += red[0][i]; t2 += red[1][i]; }
        red[0][0] = t1; red[1][0] = t2;
    }
    __syncthreads();
    float mean = red[0][0] * (1.f / DD);
    float var  = red[1][0] * (1.f / DD) - mean * mean;
    float rstd = rsqrtf(var + 1e-5f);
    g_xn[((size_t)(b * LL + l)) * DD + d] = (rv - mean) * rstd * ng[d] + nb[d];
}

// ---------------- generic fp32 tiled GEMM: C = A @ W^T + bias (+epilogue) --
// A: MxKd row-major; W: NxKd row-major. DUAL: per-row weight select.
// EPI: 0 = bias only; 1 = bias + exact gelu; 2 = bias + residual add.
#define BM 64
#define BN 64
#define BKS 16

template <bool DUAL, int EPI>
__global__ __launch_bounds__(256) void gemm_kernel(
    const float* __restrict__ A, const float* __restrict__ W0,
    const float* __restrict__ W1, const int* __restrict__ rowsel,
    const float* __restrict__ b0, const float* __restrict__ b1,
    const float* __restrict__ res, float* __restrict__ C,
    int M, int N, int Kd)
{
    __shared__ float As[BKS][BM + 4];
    __shared__ float Ws[2][BKS][BN + 4];

    int tid = threadIdx.x;
    int m0 = blockIdx.y * BM;
    int n0 = blockIdx.x * BN;
    int rowg = (tid >> 4) << 2;   // 0..60
    int colg = (tid & 15) << 2;   // 0..60
    int lrow = tid >> 2;          // 0..63
    int lk4  = tid & 3;           // 0..3

    int seli[4];
    #pragma unroll
    for (int i = 0; i < 4; i++) {
        if (DUAL) {
            int gm = m0 + rowg + i;
            if (gm >= M) gm = M - 1;
            seli[i] = rowsel[gm] ? 0 : 1;
        } else seli[i] = 0;
    }

    float acc[4][4] = {};

    for (int k0 = 0; k0 < Kd; k0 += BKS) {
        // stage A (guard rows)
        {
            int gm = m0 + lrow;
            float4 av = make_float4(0.f, 0.f, 0.f, 0.f);
            if (gm < M) av = *(const float4*)(A + (size_t)gm * Kd + k0 + lk4 * 4);
            As[lk4 * 4 + 0][lrow] = av.x;
            As[lk4 * 4 + 1][lrow] = av.y;
            As[lk4 * 4 + 2][lrow] = av.z;
            As[lk4 * 4 + 3][lrow] = av.w;
        }
        // stage W (N always multiple of 64)
        {
            int gn = n0 + lrow;
            float4 wv = *(const float4*)(W0 + (size_t)gn * Kd + k0 + lk4 * 4);
            Ws[0][lk4 * 4 + 0][lrow] = wv.x;
            Ws[0][lk4 * 4 + 1][lrow] = wv.y;
            Ws[0][lk4 * 4 + 2][lrow] = wv.z;
            Ws[0][lk4 * 4 + 3][lrow] = wv.w;
            if (DUAL) {
                float4 w2 = *(const float4*)(W1 + (size_t)gn * Kd + k0 + lk4 * 4);
                Ws[1][lk4 * 4 + 0][lrow] = w2.x;
                Ws[1][lk4 * 4 + 1][lrow] = w2.y;
                Ws[1][lk4 * 4 + 2][lrow] = w2.z;
                Ws[1][lk4 * 4 + 3][lrow] = w2.w;
            }
        }
        __syncthreads();

        #pragma unroll
        for (int kk = 0; kk < BKS; kk++) {
            float a[4];
            #pragma unroll
            for (int i = 0; i < 4; i++) a[i] = As[kk][rowg + i];
            if (!DUAL) {
                float w[4];
                #pragma unroll
                for (int j = 0; j < 4; j++) w[j] = Ws[0][kk][colg + j];
                #pragma unroll
                for (int i = 0; i < 4; i++)
                    #pragma unroll
                    for (int j = 0; j < 4; j++)
                        acc[i][j] += a[i] * w[j];
            } else {
                #pragma unroll
                for (int i = 0; i < 4; i++) {
                    const float* wp = &Ws[seli[i]][kk][colg];
                    #pragma unroll
                    for (int j = 0; j < 4; j++)
                        acc[i][j] += a[i] * wp[j];
                }
            }
        }
        __syncthreads();
    }

    #pragma unroll
    for (int i = 0; i < 4; i++) {
        int gm = m0 + rowg + i;
        if (gm >= M) continue;
        const float* bp = DUAL ? (seli[i] == 0 ? b0 : b1) : b0;
        #pragma unroll
        for (int j = 0; j < 4; j++) {
            int gn = n0 + colg + j;
            float v = acc[i][j] + bp[gn];
            if (EPI == 1) v = 0.5f * v * (1.0f + erff(v * 0.70710678118654752f));
            if (EPI == 2) v += res[(size_t)gm * N + gn];
            C[(size_t)gm * N + gn] = v;
        }
    }
}

// ---------------- attention: per-query selected block, key-masked ---------
__global__ __launch_bounds__(128) void attn_kernel(
    const float* __restrict__ bqkv_c, const float* __restrict__ bqkv_t)
{
    int qc = blockIdx.x;     // 0..7 (128 queries each)
    int h  = blockIdx.y;     // head
    int b  = blockIdx.z;     // batch
    int tid = threadIdx.x;   // 128
    int k = qc * 128 + tid;

    int sel = g_isctx[b * KK + k];                 // 1 => ctx block
    const float* qkv  = sel ? g_qkv_c : g_qkv_t;
    const float* bqkv = sel ? bqkv_c  : bqkv_t;

    const float scale = 0.1767766952966369f;       // 1/sqrt(32)
    float q[HD];
    {
        const float* qp = qkv + ((size_t)(b * LL + RR + k)) * (3 * DD) + h * HD;
        #pragma unroll
        for (int i = 0; i < HD; i++) q[i] = qp[i] * scale;
    }

    float m = -1e30f, ssum = 0.f;
    float acc[HD];
    #pragma unroll
    for (int i = 0; i < HD; i++) acc[i] = 0.f;

    __shared__ float sK[2][32][HD];
    __shared__ float sV[2][32][HD];
    __shared__ int sA[32];

    const float (*Kp)[HD] = sel ? sK[0] : sK[1];
    const float (*Vp)[HD] = sel ? sV[0] : sV[1];

    for (int l0 = 0; l0 < LL; l0 += 32) {
        int cnt = min(32, LL - l0);
        __syncthreads();
        if (tid < 32) sA[tid] = (l0 + tid < LL) ? g_allowed[b * LL + l0 + tid] : 0;
        #pragma unroll
        for (int jj = 0; jj < 2; jj++) {
            int idx = tid * 2 + jj;        // 0..255
            int kk = idx >> 3, i4 = idx & 7;
            if (l0 + kk < LL) {
                size_t base = ((size_t)(b * LL + l0 + kk)) * (3 * DD) + h * HD + i4 * 4;
                *(float4*)&sK[0][kk][i4 * 4] = *(const float4*)(g_qkv_c + base + DD);
                *(float4*)&sK[1][kk][i4 * 4] = *(const float4*)(g_qkv_t + base + DD);
                *(float4*)&sV[0][kk][i4 * 4] = *(const float4*)(g_qkv_c + base + 2 * DD);
                *(float4*)&sV[1][kk][i4 * 4] = *(const float4*)(g_qkv_t + base + 2 * DD);
            }
        }
        __syncthreads();

        for (int kk = 0; kk < cnt; kk++) {
            if (!sA[kk]) continue;         // uniform branch (mask is per-key)
            float s = 0.f;
            #pragma unroll
            for (int i = 0; i < HD; i++) s += q[i] * Kp[kk][i];
            if (s <= m) {
                float p = __expf(s - m);
                ssum += p;
                #pragma unroll
                for (int i = 0; i < HD; i++) acc[i] += p * Vp[kk][i];
            } else {
                float corr = __expf(m - s);
                ssum = ssum * corr + 1.f;
                #pragma unroll
                for (int i = 0; i < HD; i++) acc[i] = acc[i] * corr + Vp[kk][i];
                m = s;
            }
        }
    }

    // appended bias-only key (always allowed): k_row = bk, v_row = bv
    {
        float s = 0.f;
        #pragma unroll
        for (int i = 0; i < HD; i++) s += q[i] * bqkv[DD + h * HD + i];
        if (s <= m) {
            float p = __expf(s - m);
            ssum += p;
            #pragma unroll
            for (int i = 0; i < HD; i++) acc[i] += p * bqkv[2 * DD + h * HD + i];
        } else {
            float corr = __expf(m - s);
            ssum = ssum * corr + 1.f;
            #pragma unroll
            for (int i = 0; i < HD; i++) acc[i] = acc[i] * corr + bqkv[2 * DD + h * HD + i];
            m = s;
        }
    }

    float inv = 1.f / ssum;
    float* op = g_attn + ((size_t)(b * KK + k)) * DD + h * HD;
    #pragma unroll
    for (int i = 0; i < HD; i++) op[i] = acc[i] * inv;
}

// ---------------- residual add + LN (for MLP input) ------------------------
__global__ __launch_bounds__(256) void resln_kernel(
    const float* __restrict__ gn, const float* __restrict__ bn)
{
    int mrow = blockIdx.x;           // 0..8191
    int d = threadIdx.x;
    int b = mrow >> 10, k = mrow & 1023;

    __shared__ float red[2][8];
    float v = g_xfull[((size_t)(b * LL + RR + k)) * DD + d] + g_tmp[(size_t)mrow * DD + d];
    g_x2[(size_t)mrow * DD + d] = v;

    float s1 = v, s2 = v * v;
    #pragma unroll
    for (int o = 16; o; o >>= 1) {
        s1 += __shfl_down_sync(0xffffffffu, s1, o);
        s2 += __shfl_down_sync(0xffffffffu, s2, o);
    }
    int wid = d >> 5, lane = d & 31;
    if (lane == 0) { red[0][wid] = s1; red[1][wid] = s2; }
    __syncthreads();
    if (d == 0) {
        float t1 = 0.f, t2 = 0.f;
        #pragma unroll
        for (int i = 0; i < 8; i++) { t1 += red[0][i]; t2 += red[1][i]; }
        red[0][0] = t1; red[1][0] = t2;
    }
    __syncthreads();
    float mean = red[0][0] * (1.f / DD);
    float var  = red[1][0] * (1.f / DD) - mean * mean;
    float rstd = rsqrtf(var + 1e-5f);
    g_x2n[(size_t)mrow * DD + d] = (v - mean) * rstd * gn[d] + bn[d];
}

// ---------------- launch ----------------------------------------------------
static void* sym(const void* s)
{
    void* p = nullptr;
    cudaGetSymbolAddress(&p, s);
    return p;
}

extern "C" void kernel_launch(void* const* d_in, const int* in_sizes, int n_in,
                              void* d_out, int out_size)
{
    const float* x          = (const float*)d_in[0];
    const int*   coords     = (const int*)d_in[1];
    const int*   ctxid      = (const int*)d_in[2];
    const float* tgt_e      = (const float*)d_in[3];
    const float* ctx_e      = (const float*)d_in[4];
    const float* regs       = (const float*)d_in[5];
    const float* rope       = (const float*)d_in[6];
    const float* norm_g     = (const float*)d_in[7];
    const float* norm_b     = (const float*)d_in[8];
    const float* ctx_Wqkv   = (const float*)d_in[9];
    const float* ctx_bqkv   = (const float*)d_in[10];
    const float* ctx_Wo     = (const float*)d_in[11];
    const float* ctx_bo     = (const float*)d_in[12];
    const float* tgt_Wqkv   = (const float*)d_in[13];
    const float* tgt_bqkv   = (const float*)d_in[14];
    const float* tgt_Wo     = (const float*)d_in[15];
    const float* tgt_bo     = (const float*)d_in[16];
    const float* mlpn_g     = (const float*)d_in[17];
    const float* mlpn_b     = (const float*)d_in[18];
    const float* mlp_W1     = (const float*)d_in[19];
    const float* mlp_b1     = (const float*)d_in[20];
    const float* mlp_W2     = (const float*)d_in[21];
    const float* mlp_b2     = (const float*)d_in[22];
    float* out = (float*)d_out;

    float* p_xn   = (float*)sym(g_xn);
    float* p_qc   = (float*)sym(g_qkv_c);
    float* p_qt   = (float*)sym(g_qkv_t);
    float* p_attn = (float*)sym(g_attn);
    float* p_tmp  = (float*)sym(g_tmp);
    float* p_x2   = (float*)sym(g_x2);
    float* p_x2n  = (float*)sym(g_x2n);
    float* p_h1   = (float*)sym(g_h1);
    int*   p_sel  = (int*)sym(g_isctx);

    // 1) embed + rope + LN
    prep_kernel<<<BB * LL, 256>>>(x, coords, ctxid, tgt_e, ctx_e, regs, rope,
                                  norm_g, norm_b);

    // 2) QKV for both blocks (dense over all L rows)
    {
        dim3 g((3 * DD) / BN, (BB * LL + BM - 1) / BM);
        gemm_kernel<false, 0><<<g, 256>>>(p_xn, ctx_Wqkv, nullptr, nullptr,
                                          ctx_bqkv, nullptr, nullptr, p_qc,
                                          BB * LL, 3 * DD, DD);
        gemm_kernel<false, 0><<<g, 256>>>(p_xn, tgt_Wqkv, nullptr, nullptr,
                                          tgt_bqkv, nullptr, nullptr, p_qt,
                                          BB * LL, 3 * DD, DD);
    }

    // 3) attention (per-query block selection, key-masked, online softmax)
    {
        dim3 g(KK / 128, HH, BB);
        attn_kernel<<<g, 128>>>(ctx_bqkv, tgt_bqkv);
    }

    // 4) Wo with per-row weight selection
    {
        dim3 g(DD / BN, (BB * KK) / BM);
        gemm_kernel<true, 0><<<g, 256>>>(p_attn, ctx_Wo, tgt_Wo, p_sel,
                                         ctx_bo, tgt_bo, nullptr, p_tmp,
                                         BB * KK, DD, DD);
    }

    // 5) residual + LN
    resln_kernel<<<BB * KK, 256>>>(mlpn_g, mlpn_b);

    // 6) MLP up + gelu
    {
        dim3 g((4 * DD) / BN, (BB * KK) / BM);
        gemm_kernel<false, 1><<<g, 256>>>(p_x2n, mlp_W1, nullptr, nullptr,
                                          mlp_b1, nullptr, nullptr, p_h1,
                                          BB * KK, 4 * DD, DD);
    }

    // 7) MLP down + residual -> output
    {
        dim3 g(DD / BN, (BB * KK) / BM);
        gemm_kernel<false, 2><<<g, 256>>>(p_h1, mlp_W2, nullptr, nullptr,
                                          mlp_b2, nullptr, p_x2, out,
                                          BB * KK, DD, 4 * DD);
    }
}